// round 7
// baseline (speedup 1.0000x reference)
#include <cuda_runtime.h>
#include <cuda_fp16.h>
#include <math.h>
#include <stdint.h>

#define Nn 10000
#define Ee 160000
#define NFd 5
#define EFd 3
#define Hh 8
#define Cc 128
#define HCd 1024
#define Gg 16

// ---------------- scratch -----------------------------------------------
__device__ float g_xl[Nn * HCd];
__device__ __half g_xh[Nn * HCd];     // fp16 mirror of g_xl for gathers
__device__ float g_hA[Nn * HCd];
__device__ float g_hB[Nn * HCd];
__device__ float g_Wr[HCd * HCd];
__device__ float g_asrc[Nn * Hh];
__device__ float g_adst[Nn * Hh];
__device__ float g_m[Nn * Hh];
__device__ float g_selfae[Nn * Hh];
__device__ float g_loop[Nn * EFd];
__device__ float g_loopsum[Nn * EFd];
__device__ int   g_deg[Nn];
__device__ int   g_off[Nn + 1];
__device__ int   g_cur[Nn];
__device__ int   g_eid[Ee];
__device__ int   g_csrc[Ee];
__device__ float g_v[EFd * Hh];
__device__ float g_h4[Nn * Cc];
__device__ int   g_gstart[Gg];
__device__ int   g_gcnt[Gg];

__device__ __forceinline__ float lrelu(float x) { return x > 0.f ? x : 0.2f * x; }

__device__ __forceinline__ float tf32r(float f) {
    uint32_t r;
    asm("cvt.rna.tf32.f32 %0, %1;" : "=r"(r) : "f"(f));
    return __uint_as_float(r);
}

// ---------------- precompute --------------------------------------------
__global__ void k_initg() {
    int g = threadIdx.x;
    if (g < Gg) g_gstart[g] = Nn;
}

__global__ void k_deg(const int* __restrict__ ei, const float* __restrict__ ea) {
    int e = blockIdx.x * blockDim.x + threadIdx.x;
    if (e >= Ee) return;
    int d = ei[Ee + e];
    atomicAdd(&g_deg[d], 1);
    atomicAdd(&g_loopsum[d * 3 + 0], ea[e * 3 + 0]);
    atomicAdd(&g_loopsum[d * 3 + 1], ea[e * 3 + 1]);
    atomicAdd(&g_loopsum[d * 3 + 2], ea[e * 3 + 2]);
}

__global__ void k_scan() {
    __shared__ int tmp[256];
    __shared__ int carry;
    if (threadIdx.x == 0) { carry = 0; g_off[0] = 0; }
    __syncthreads();
    for (int base = 0; base < Nn; base += 256) {
        int i = base + threadIdx.x;
        int v = (i < Nn) ? g_deg[i] : 0;
        tmp[threadIdx.x] = v;
        __syncthreads();
        for (int s = 1; s < 256; s <<= 1) {
            int t = (threadIdx.x >= s) ? tmp[threadIdx.x - s] : 0;
            __syncthreads();
            tmp[threadIdx.x] += t;
            __syncthreads();
        }
        if (i < Nn) g_off[i + 1] = carry + tmp[threadIdx.x];
        __syncthreads();
        if (threadIdx.x == 0) carry += tmp[255];
        __syncthreads();
    }
}

__global__ void k_fill(const int* __restrict__ ei) {
    int e = blockIdx.x * blockDim.x + threadIdx.x;
    if (e >= Ee) return;
    int d = ei[Ee + e];
    int p = atomicAdd(&g_cur[d], 1);
    int slot = g_off[d] + p;
    g_eid[slot] = e;
    g_csrc[slot] = ei[e];
}

__global__ void k_loop() {
    int n = blockIdx.x * blockDim.x + threadIdx.x;
    if (n >= Nn) return;
    float inv = 1.f / (float)max(g_deg[n], 1);
    g_loop[n * 3 + 0] = g_loopsum[n * 3 + 0] * inv;
    g_loop[n * 3 + 1] = g_loopsum[n * 3 + 1] * inv;
    g_loop[n * 3 + 2] = g_loopsum[n * 3 + 2] * inv;
}

__global__ void k_bounds(const int* __restrict__ batch) {
    int n = blockIdx.x * blockDim.x + threadIdx.x;
    if (n >= Nn) return;
    int b = batch[n];
    atomicAdd(&g_gcnt[b], 1);
    atomicMin(&g_gstart[b], n);
}

// ---------------- layer-1 GEMM (K = 5) ----------------------------------
__global__ void k_gemm_small(const float* __restrict__ x, const float* __restrict__ W,
                             float* __restrict__ out, __half* __restrict__ outh) {
    int idx = blockIdx.x * blockDim.x + threadIdx.x;
    if (idx >= Nn * HCd) return;
    int n = idx >> 10, j = idx & 1023;
    float s = 0.f;
#pragma unroll
    for (int f = 0; f < NFd; f++) s += x[n * NFd + f] * W[f * HCd + j];
    out[idx] = s;
    outh[idx] = __float2half_rn(s);
}

// ---------------- tf32 rounding for W -----------------------------------
__global__ void k_round(const float* __restrict__ W, float* __restrict__ Wr) {
    int i = blockIdx.x * blockDim.x + threadIdx.x;
    if (i < HCd * HCd) Wr[i] = tf32r(W[i]);
}

// ---------------- tf32 mma.sync GEMM, 3-stage pipeline ------------------
#define MM_BK 32
#define MM_NT (HCd / MM_BK)
#define MM_ST 3
#define MM_ASTR 36
#define MM_BSTR 136
#define MM_STAGEF (128 * MM_ASTR + MM_BK * MM_BSTR)
#define MM_SMEM (MM_ST * MM_STAGEF * 4)

__device__ __forceinline__ uint32_t s2u(const void* p) {
    uint32_t a;
    asm("{ .reg .u64 t; cvta.to.shared.u64 t, %1; cvt.u32.u64 %0, t; }" : "=r"(a) : "l"(p));
    return a;
}

__device__ __forceinline__ void mma8(float* c, const uint32_t* a, const uint32_t* b) {
    asm volatile(
        "mma.sync.aligned.m16n8k8.row.col.f32.tf32.tf32.f32 "
        "{%0,%1,%2,%3}, {%4,%5,%6,%7}, {%8,%9}, {%0,%1,%2,%3};"
        : "+f"(c[0]), "+f"(c[1]), "+f"(c[2]), "+f"(c[3])
        : "r"(a[0]), "r"(a[1]), "r"(a[2]), "r"(a[3]), "r"(b[0]), "r"(b[1]));
}

__global__ __launch_bounds__(256)
void k_mma(const float* __restrict__ A, const float* __restrict__ B,
           float* __restrict__ C, __half* __restrict__ Ch, int M) {
    extern __shared__ __align__(16) float smem[];
    const int tid = threadIdx.x, wid = tid >> 5, lane = tid & 31;
    const int warp_m = wid & 3, warp_n = wid >> 2;
    const int row0 = blockIdx.y * 128, col0 = blockIdx.x * 128;
    const int lg = lane >> 2, lk = lane & 3;

    float acc[2][8][4];
#pragma unroll
    for (int mf = 0; mf < 2; mf++)
#pragma unroll
        for (int nf = 0; nf < 8; nf++)
#pragma unroll
            for (int q = 0; q < 4; q++) acc[mf][nf][q] = 0.f;

    const int ar = tid >> 3, ac = tid & 7;
    const int br = tid >> 3, bc = tid & 7;

    // stage loader
    auto load_stage = [&](int st, int k0) {
        float* sA = smem + st * MM_STAGEF;
        float* sB = sA + 128 * MM_ASTR;
#pragma unroll
        for (int i = 0; i < 4; i++) {
            int r = ar + i * 32;
            uint32_t d = s2u(sA) + (r * MM_ASTR + ac * 4) * 4;
            int gr = row0 + r;
            if (gr < M)
                asm volatile("cp.async.cg.shared.global [%0], [%1], 16;"
                             :: "r"(d), "l"(A + (size_t)gr * HCd + k0 + ac * 4));
            else
                asm volatile("st.shared.v4.b32 [%0], {%1,%1,%1,%1};" :: "r"(d), "r"(0u) : "memory");
        }
#pragma unroll
        for (int j = 0; j < 4; j++) {
            uint32_t d = s2u(sB) + (br * MM_BSTR + bc * 4 + j * 32) * 4;
            asm volatile("cp.async.cg.shared.global [%0], [%1], 16;"
                         :: "r"(d), "l"(B + (size_t)(k0 + br) * HCd + col0 + bc * 4 + j * 32));
        }
    };

    // prologue: stages 0,1
    load_stage(0, 0);
    asm volatile("cp.async.commit_group;" ::: "memory");
    load_stage(1, MM_BK);
    asm volatile("cp.async.commit_group;" ::: "memory");

    for (int kt = 0; kt < MM_NT; kt++) {
        if (kt + 2 < MM_NT) load_stage((kt + 2) % MM_ST, (kt + 2) * MM_BK);
        asm volatile("cp.async.commit_group;" ::: "memory");
        asm volatile("cp.async.wait_group 2;" ::: "memory");
        __syncthreads();

        const float* sA = smem + (kt % MM_ST) * MM_STAGEF;
        const float* sB = sA + 128 * MM_ASTR;
#pragma unroll
        for (int ks = 0; ks < 4; ks++) {
            uint32_t af[2][4], bf[8][2];
#pragma unroll
            for (int mf = 0; mf < 2; mf++) {
                int m = warp_m * 32 + mf * 16 + lg;
                int k = ks * 8 + lk;
                af[mf][0] = __float_as_uint(sA[m * MM_ASTR + k]);
                af[mf][1] = __float_as_uint(sA[(m + 8) * MM_ASTR + k]);
                af[mf][2] = __float_as_uint(sA[m * MM_ASTR + k + 4]);
                af[mf][3] = __float_as_uint(sA[(m + 8) * MM_ASTR + k + 4]);
            }
#pragma unroll
            for (int nf = 0; nf < 8; nf++) {
                int n = warp_n * 64 + nf * 8 + lg;
                int k = ks * 8 + lk;
                bf[nf][0] = __float_as_uint(sB[k * MM_BSTR + n]);
                bf[nf][1] = __float_as_uint(sB[(k + 4) * MM_BSTR + n]);
            }
#pragma unroll
            for (int mf = 0; mf < 2; mf++)
#pragma unroll
                for (int nf = 0; nf < 8; nf++) mma8(acc[mf][nf], af[mf], bf[nf]);
        }
        __syncthreads();
    }

#pragma unroll
    for (int mf = 0; mf < 2; mf++) {
        int r0 = row0 + warp_m * 32 + mf * 16 + lg;
        int r1 = r0 + 8;
#pragma unroll
        for (int nf = 0; nf < 8; nf++) {
            int ccol = col0 + warp_n * 64 + nf * 8 + 2 * lk;
            if (r0 < M) {
                *(float2*)(C + (size_t)r0 * HCd + ccol) =
                    make_float2(acc[mf][nf][0], acc[mf][nf][1]);
                *(__half2*)(Ch + (size_t)r0 * HCd + ccol) =
                    __floats2half2_rn(acc[mf][nf][0], acc[mf][nf][1]);
            }
            if (r1 < M) {
                *(float2*)(C + (size_t)r1 * HCd + ccol) =
                    make_float2(acc[mf][nf][2], acc[mf][nf][3]);
                *(__half2*)(Ch + (size_t)r1 * HCd + ccol) =
                    __floats2half2_rn(acc[mf][nf][2], acc[mf][nf][3]);
            }
        }
    }
}

// ---------------- attention pieces --------------------------------------
__global__ void k_attn(const float* __restrict__ xl, const float* __restrict__ a_s,
                       const float* __restrict__ a_d) {
    int gw = (blockIdx.x * blockDim.x + threadIdx.x) >> 5;
    int lane = threadIdx.x & 31;
    if (gw >= Nn * Hh) return;
    int n = gw >> 3, h = gw & 7;
    float4 xv = *(const float4*)(xl + (size_t)n * HCd + h * Cc + lane * 4);
    float4 sv = *(const float4*)(a_s + h * Cc + lane * 4);
    float4 dv = *(const float4*)(a_d + h * Cc + lane * 4);
    float s1 = xv.x * sv.x + xv.y * sv.y + xv.z * sv.z + xv.w * sv.w;
    float s2 = xv.x * dv.x + xv.y * dv.y + xv.z * dv.z + xv.w * dv.w;
#pragma unroll
    for (int o = 16; o; o >>= 1) {
        s1 += __shfl_xor_sync(0xffffffffu, s1, o);
        s2 += __shfl_xor_sync(0xffffffffu, s2, o);
    }
    if (lane == 0) {
        g_asrc[n * 8 + h] = s1;
        g_adst[n * 8 + h] = s2;
    }
}

__global__ void k_v(const float* __restrict__ We, const float* __restrict__ ae) {
    int w = threadIdx.x >> 5, lane = threadIdx.x & 31;
    if (w >= 24) return;
    int f = w >> 3, h = w & 7;
    float s = 0.f;
    for (int i = lane; i < Cc; i += 32) s += We[f * HCd + h * Cc + i] * ae[h * Cc + i];
#pragma unroll
    for (int o = 16; o; o >>= 1) s += __shfl_xor_sync(0xffffffffu, s, o);
    if (lane == 0) g_v[f * 8 + h] = s;
}

__global__ void k_aes() {
    int n = blockIdx.x * blockDim.x + threadIdx.x;
    if (n >= Nn) return;
    float a0 = g_loop[n * 3 + 0], a1 = g_loop[n * 3 + 1], a2 = g_loop[n * 3 + 2];
#pragma unroll
    for (int h = 0; h < 8; h++)
        g_selfae[n * 8 + h] = a0 * g_v[h] + a1 * g_v[8 + h] + a2 * g_v[16 + h];
}

__global__ void k_max(const float* __restrict__ ea) {
    int gw = (blockIdx.x * blockDim.x + threadIdx.x) >> 5;
    int lane = threadIdx.x & 31;
    if (gw >= Nn) return;
    int n = gw;
    float vv[24];
#pragma unroll
    for (int i = 0; i < 24; i++) vv[i] = g_v[i];
    float4 ad0 = *(const float4*)&g_adst[n * 8];
    float4 ad1 = *(const float4*)&g_adst[n * 8 + 4];
    float ad[8] = {ad0.x, ad0.y, ad0.z, ad0.w, ad1.x, ad1.y, ad1.z, ad1.w};
    float4 s0 = *(const float4*)&g_asrc[n * 8];
    float4 s1 = *(const float4*)&g_asrc[n * 8 + 4];
    float as[8] = {s0.x, s0.y, s0.z, s0.w, s1.x, s1.y, s1.z, s1.w};
    float4 e0 = *(const float4*)&g_selfae[n * 8];
    float4 e1 = *(const float4*)&g_selfae[n * 8 + 4];
    float se[8] = {e0.x, e0.y, e0.z, e0.w, e1.x, e1.y, e1.z, e1.w};
    float mx[8];
#pragma unroll
    for (int h = 0; h < 8; h++) mx[h] = lrelu(as[h] + ad[h] + se[h]);
    int s = g_off[n], t = g_off[n + 1];
    for (int idx = s + lane; idx < t; idx += 32) {
        int e = g_eid[idx];
        int sn = g_csrc[idx];
        float4 a0 = *(const float4*)&g_asrc[sn * 8];
        float4 a1 = *(const float4*)&g_asrc[sn * 8 + 4];
        float an[8] = {a0.x, a0.y, a0.z, a0.w, a1.x, a1.y, a1.z, a1.w};
        float q0 = ea[e * 3 + 0], q1 = ea[e * 3 + 1], q2 = ea[e * 3 + 2];
#pragma unroll
        for (int h = 0; h < 8; h++) {
            float aeh = q0 * vv[h] + q1 * vv[8 + h] + q2 * vv[16 + h];
            mx[h] = fmaxf(mx[h], lrelu(an[h] + ad[h] + aeh));
        }
    }
#pragma unroll
    for (int h = 0; h < 8; h++)
#pragma unroll
        for (int o = 16; o; o >>= 1) mx[h] = fmaxf(mx[h], __shfl_xor_sync(0xffffffffu, mx[h], o));
    if (lane == 0) {
        *(float4*)&g_m[n * 8] = make_float4(mx[0], mx[1], mx[2], mx[3]);
        *(float4*)&g_m[n * 8 + 4] = make_float4(mx[4], mx[5], mx[6], mx[7]);
    }
}

// block per node; warp = head; lane owns 4 consecutive cols; gathers fp16
__global__ __launch_bounds__(256) void k_agg(const float* __restrict__ xl,
                                             const __half* __restrict__ xh,
                                             const float* __restrict__ ea,
                                             const float* __restrict__ bias,
                                             float* __restrict__ out, int mode) {
    int n = blockIdx.x;
    int lane = threadIdx.x & 31;
    int h = threadIdx.x >> 5;
    int col = h * Cc + lane * 4;

    float vh0 = g_v[h], vh1 = g_v[8 + h], vh2 = g_v[16 + h];
    float adh = g_adst[n * 8 + h];
    float mh = g_m[n * 8 + h];
    float ash = g_asrc[n * 8 + h];
    float sae = g_selfae[n * 8 + h];

    float ws = __expf(lrelu(ash + adh + sae) - mh);
    float4 xv = *(const float4*)(xl + (size_t)n * HCd + col);
    float4 acc = make_float4(ws * xv.x, ws * xv.y, ws * xv.z, ws * xv.w);
    float den = ws;

    int s = g_off[n], tend = g_off[n + 1];
#pragma unroll 2
    for (int idx = s; idx < tend; idx++) {
        int e = g_eid[idx];
        int sn = g_csrc[idx];
        float q0 = ea[e * 3 + 0], q1 = ea[e * 3 + 1], q2 = ea[e * 3 + 2];
        float asn = g_asrc[sn * 8 + h];
        float aeh = q0 * vh0 + q1 * vh1 + q2 * vh2;
        float w = __expf(lrelu(asn + adh + aeh) - mh);
        uint2 raw = *(const uint2*)(xh + (size_t)sn * HCd + col);
        float2 f0 = __half22float2(*(const __half2*)&raw.x);
        float2 f1 = __half22float2(*(const __half2*)&raw.y);
        acc.x += w * f0.x;
        acc.y += w * f0.y;
        acc.z += w * f1.x;
        acc.w += w * f1.y;
        den += w;
    }

    float inv = 1.f / (den + 1e-16f);
    float4 v = make_float4(acc.x * inv, acc.y * inv, acc.z * inv, acc.w * inv);
    if (mode == 0) {
        float4 b = *(const float4*)(bias + col);
        v.x += b.x; v.y += b.y; v.z += b.z; v.w += b.w;
        v.x = v.x > 0.f ? v.x : expm1f(v.x);
        v.y = v.y > 0.f ? v.y : expm1f(v.y);
        v.z = v.z > 0.f ? v.z : expm1f(v.z);
        v.w = v.w > 0.f ? v.w : expm1f(v.w);
        v.x = tf32r(v.x); v.y = tf32r(v.y); v.z = tf32r(v.z); v.w = tf32r(v.w);
    }
    *(float4*)(out + (size_t)n * HCd + col) = v;
}

__global__ void k_head(const float* __restrict__ tmp, const float* __restrict__ b4) {
    int idx = blockIdx.x * blockDim.x + threadIdx.x;
    if (idx >= Nn * Cc) return;
    int n = idx >> 7, c = idx & 127;
    float s = 0.f;
#pragma unroll
    for (int h = 0; h < 8; h++) s += tmp[(size_t)n * HCd + h * Cc + c];
    float v = s * 0.125f + b4[c];
    g_h4[idx] = v > 0.f ? v : expm1f(v);
}

__global__ void k_pool(const float* __restrict__ lw, const float* __restrict__ lb,
                       float* __restrict__ outp) {
    int g = blockIdx.x, c = threadIdx.x;
    int s = g_gstart[g], cnt = g_gcnt[g];
    float acc = 0.f;
    for (int i = 0; i < cnt; i++) acc += g_h4[(size_t)(s + i) * Cc + c];
    acc *= lw[c];
    __shared__ float red[128];
    red[c] = acc;
    __syncthreads();
    for (int o = 64; o; o >>= 1) {
        if (c < o) red[c] += red[c + o];
        __syncthreads();
    }
    if (c == 0) outp[g] = red[0] / fmaxf((float)cnt, 1.f) + lb[0];
}

// ---------------- launch -------------------------------------------------
static void* sym(const void* s) {
    void* p = nullptr;
    cudaGetSymbolAddress(&p, (const void*)s);
    return p;
}

extern "C" void kernel_launch(void* const* d_in, const int* in_sizes, int n_in,
                              void* d_out, int out_size) {
    (void)in_sizes; (void)n_in; (void)out_size;
    const float* x = (const float*)d_in[0];
    const int* ei = (const int*)d_in[1];
    const float* ea = (const float*)d_in[2];
    const int* batch = (const int*)d_in[3];
    const float *W[4], *We[4], *As_[4], *Ad_[4], *Ae_[4], *Bb[4];
    for (int l = 0; l < 4; l++) {
        W[l]   = (const float*)d_in[4 + 6 * l + 0];
        We[l]  = (const float*)d_in[4 + 6 * l + 1];
        As_[l] = (const float*)d_in[4 + 6 * l + 2];
        Ad_[l] = (const float*)d_in[4 + 6 * l + 3];
        Ae_[l] = (const float*)d_in[4 + 6 * l + 4];
        Bb[l]  = (const float*)d_in[4 + 6 * l + 5];
    }
    const float* lw = (const float*)d_in[28];
    const float* lb = (const float*)d_in[29];
    float* outp = (float*)d_out;

    float* xl = (float*)sym(&g_xl);
    __half* xh = (__half*)sym(&g_xh);
    float* hA = (float*)sym(&g_hA);
    float* hB = (float*)sym(&g_hB);
    float* Wr = (float*)sym(&g_Wr);

    cudaFuncSetAttribute(k_mma, cudaFuncAttributeMaxDynamicSharedMemorySize, MM_SMEM);

    cudaMemsetAsync(sym(&g_deg), 0, Nn * sizeof(int));
    cudaMemsetAsync(sym(&g_loopsum), 0, Nn * EFd * sizeof(float));
    cudaMemsetAsync(sym(&g_cur), 0, Nn * sizeof(int));
    cudaMemsetAsync(sym(&g_gcnt), 0, Gg * sizeof(int));
    k_initg<<<1, 32>>>();
    k_deg<<<(Ee + 255) / 256, 256>>>(ei, ea);
    k_scan<<<1, 256>>>();
    k_fill<<<(Ee + 255) / 256, 256>>>(ei);
    k_loop<<<(Nn + 255) / 256, 256>>>();
    k_bounds<<<(Nn + 255) / 256, 256>>>(batch);

    for (int l = 0; l < 4; l++) {
        const float* inp = (l == 0) ? x : ((l == 1) ? hA : ((l == 2) ? hB : hA));
        float* hout = (l == 0) ? hA : ((l == 1) ? hB : ((l == 2) ? hA : hB));

        if (l == 0) {
            k_gemm_small<<<(Nn * HCd + 255) / 256, 256>>>(x, W[0], xl, xh);
        } else {
            k_round<<<(HCd * HCd + 255) / 256, 256>>>(W[l], Wr);
            k_mma<<<dim3(HCd / 128, (Nn + 127) / 128), 256, MM_SMEM>>>(inp, Wr, xl, xh, Nn);
        }

        k_attn<<<(Nn * Hh * 32 + 255) / 256, 256>>>(xl, As_[l], Ad_[l]);
        k_v<<<1, 768>>>(We[l], Ae_[l]);
        k_aes<<<(Nn + 255) / 256, 256>>>();
        k_max<<<(Nn * 32 + 255) / 256, 256>>>(ea);
        k_agg<<<Nn, 256>>>(xl, xh, ea, Bb[l], hout, (l < 3) ? 0 : 1);
        if (l == 3) k_head<<<(Nn * Cc + 255) / 256, 256>>>(hB, Bb[3]);
    }
    k_pool<<<Gg, 128>>>(lw, lb, outp);
}

// round 8
// speedup vs baseline: 1.0568x; 1.0568x over previous
#include <cuda_runtime.h>
#include <math.h>
#include <stdint.h>

#define Nn 10000
#define Ee 160000
#define NFd 5
#define EFd 3
#define Hh 8
#define Cc 128
#define HCd 1024
#define Gg 16

// ---------------- scratch -----------------------------------------------
__device__ float g_xl[Nn * HCd];
__device__ float g_hA[Nn * HCd];
__device__ float g_hB[Nn * HCd];
__device__ float g_Wr[HCd * HCd];
__device__ float g_asrc[Nn * Hh];
__device__ float g_adst[Nn * Hh];
__device__ float g_loop[Nn * EFd];
__device__ float g_loopsum[Nn * EFd];
__device__ int   g_deg[Nn];
__device__ int   g_off[Nn + 1];
__device__ int   g_cur[Nn];
__device__ int   g_eid[Ee];
__device__ int   g_csrc[Ee];
__device__ float g_v[EFd * Hh];
__device__ float g_h4[Nn * Cc];
__device__ int   g_gstart[Gg];
__device__ int   g_gcnt[Gg];

__device__ __forceinline__ float lrelu(float x) { return x > 0.f ? x : 0.2f * x; }

__device__ __forceinline__ float tf32r(float f) {
    uint32_t r;
    asm("cvt.rna.tf32.f32 %0, %1;" : "=r"(r) : "f"(f));
    return __uint_as_float(r);
}

// ---------------- precompute --------------------------------------------
__global__ void k_initg() {
    int g = threadIdx.x;
    if (g < Gg) g_gstart[g] = Nn;
}

__global__ void k_deg(const int* __restrict__ ei, const float* __restrict__ ea) {
    int e = blockIdx.x * blockDim.x + threadIdx.x;
    if (e >= Ee) return;
    int d = ei[Ee + e];
    atomicAdd(&g_deg[d], 1);
    atomicAdd(&g_loopsum[d * 3 + 0], ea[e * 3 + 0]);
    atomicAdd(&g_loopsum[d * 3 + 1], ea[e * 3 + 1]);
    atomicAdd(&g_loopsum[d * 3 + 2], ea[e * 3 + 2]);
}

__global__ void k_scan() {
    __shared__ int tmp[256];
    __shared__ int carry;
    if (threadIdx.x == 0) { carry = 0; g_off[0] = 0; }
    __syncthreads();
    for (int base = 0; base < Nn; base += 256) {
        int i = base + threadIdx.x;
        int v = (i < Nn) ? g_deg[i] : 0;
        tmp[threadIdx.x] = v;
        __syncthreads();
        for (int s = 1; s < 256; s <<= 1) {
            int t = (threadIdx.x >= s) ? tmp[threadIdx.x - s] : 0;
            __syncthreads();
            tmp[threadIdx.x] += t;
            __syncthreads();
        }
        if (i < Nn) g_off[i + 1] = carry + tmp[threadIdx.x];
        __syncthreads();
        if (threadIdx.x == 0) carry += tmp[255];
        __syncthreads();
    }
}

__global__ void k_fill(const int* __restrict__ ei) {
    int e = blockIdx.x * blockDim.x + threadIdx.x;
    if (e >= Ee) return;
    int d = ei[Ee + e];
    int p = atomicAdd(&g_cur[d], 1);
    int slot = g_off[d] + p;
    g_eid[slot] = e;
    g_csrc[slot] = ei[e];
}

__global__ void k_loop() {
    int n = blockIdx.x * blockDim.x + threadIdx.x;
    if (n >= Nn) return;
    float inv = 1.f / (float)max(g_deg[n], 1);
    g_loop[n * 3 + 0] = g_loopsum[n * 3 + 0] * inv;
    g_loop[n * 3 + 1] = g_loopsum[n * 3 + 1] * inv;
    g_loop[n * 3 + 2] = g_loopsum[n * 3 + 2] * inv;
}

__global__ void k_bounds(const int* __restrict__ batch) {
    int n = blockIdx.x * blockDim.x + threadIdx.x;
    if (n >= Nn) return;
    int b = batch[n];
    atomicAdd(&g_gcnt[b], 1);
    atomicMin(&g_gstart[b], n);
}

// ---------------- layer-1 GEMM (K = 5) ----------------------------------
__global__ void k_gemm_small(const float* __restrict__ x, const float* __restrict__ W,
                             float* __restrict__ out) {
    int idx = blockIdx.x * blockDim.x + threadIdx.x;
    if (idx >= Nn * HCd) return;
    int n = idx >> 10, j = idx & 1023;
    float s = 0.f;
#pragma unroll
    for (int f = 0; f < NFd; f++) s += x[n * NFd + f] * W[f * HCd + j];
    out[idx] = s;
}

// ---------------- tf32 rounding for W -----------------------------------
__global__ void k_round(const float* __restrict__ W, float* __restrict__ Wr) {
    int i = blockIdx.x * blockDim.x + threadIdx.x;
    if (i < HCd * HCd) Wr[i] = tf32r(W[i]);
}

// ---------------- tf32 mma.sync GEMM (2-stage, as in R6) ----------------
#define MM_BK 32
#define MM_NT (HCd / MM_BK)
#define MM_ASTR 36
#define MM_BSTR 136
#define MM_STAGEF (128 * MM_ASTR + MM_BK * MM_BSTR)
#define MM_SMEM (2 * MM_STAGEF * 4)

__device__ __forceinline__ uint32_t s2u(const void* p) {
    uint32_t a;
    asm("{ .reg .u64 t; cvta.to.shared.u64 t, %1; cvt.u32.u64 %0, t; }" : "=r"(a) : "l"(p));
    return a;
}

__device__ __forceinline__ void mma8(float* c, const uint32_t* a, const uint32_t* b) {
    asm volatile(
        "mma.sync.aligned.m16n8k8.row.col.f32.tf32.tf32.f32 "
        "{%0,%1,%2,%3}, {%4,%5,%6,%7}, {%8,%9}, {%0,%1,%2,%3};"
        : "+f"(c[0]), "+f"(c[1]), "+f"(c[2]), "+f"(c[3])
        : "r"(a[0]), "r"(a[1]), "r"(a[2]), "r"(a[3]), "r"(b[0]), "r"(b[1]));
}

__global__ __launch_bounds__(256)
void k_mma(const float* __restrict__ A, const float* __restrict__ B,
           float* __restrict__ C, int M) {
    extern __shared__ __align__(16) float smem[];
    const int tid = threadIdx.x, wid = tid >> 5, lane = tid & 31;
    const int warp_m = wid & 3, warp_n = wid >> 2;
    const int row0 = blockIdx.y * 128, col0 = blockIdx.x * 128;
    const int lg = lane >> 2, lk = lane & 3;

    float acc[2][8][4];
#pragma unroll
    for (int mf = 0; mf < 2; mf++)
#pragma unroll
        for (int nf = 0; nf < 8; nf++)
#pragma unroll
            for (int q = 0; q < 4; q++) acc[mf][nf][q] = 0.f;

    const int ar = tid >> 3, ac = tid & 7;
    const int br = tid >> 3, bc = tid & 7;

    uint32_t sbase = s2u(smem);

    {
        int k0 = 0;
        float* sB = smem + 128 * MM_ASTR;
#pragma unroll
        for (int i = 0; i < 4; i++) {
            int r = ar + i * 32;
            uint32_t d = sbase + (r * MM_ASTR + ac * 4) * 4;
            int gr = row0 + r;
            if (gr < M)
                asm volatile("cp.async.cg.shared.global [%0], [%1], 16;"
                             :: "r"(d), "l"(A + (size_t)gr * HCd + k0 + ac * 4));
            else
                asm volatile("st.shared.v4.b32 [%0], {%1,%1,%1,%1};" :: "r"(d), "r"(0u) : "memory");
        }
#pragma unroll
        for (int j = 0; j < 4; j++) {
            uint32_t d = s2u(sB) + (br * MM_BSTR + bc * 4 + j * 32) * 4;
            asm volatile("cp.async.cg.shared.global [%0], [%1], 16;"
                         :: "r"(d), "l"(B + (size_t)(k0 + br) * HCd + col0 + bc * 4 + j * 32));
        }
        asm volatile("cp.async.commit_group;" ::: "memory");
    }

    for (int kt = 0; kt < MM_NT; kt++) {
        if (kt + 1 < MM_NT) {
            int k0 = (kt + 1) * MM_BK;
            float* sA = smem + ((kt + 1) & 1) * MM_STAGEF;
            float* sB = sA + 128 * MM_ASTR;
#pragma unroll
            for (int i = 0; i < 4; i++) {
                int r = ar + i * 32;
                uint32_t d = s2u(sA) + (r * MM_ASTR + ac * 4) * 4;
                int gr = row0 + r;
                if (gr < M)
                    asm volatile("cp.async.cg.shared.global [%0], [%1], 16;"
                                 :: "r"(d), "l"(A + (size_t)gr * HCd + k0 + ac * 4));
                else
                    asm volatile("st.shared.v4.b32 [%0], {%1,%1,%1,%1};" :: "r"(d), "r"(0u) : "memory");
            }
#pragma unroll
            for (int j = 0; j < 4; j++) {
                uint32_t d = s2u(sB) + (br * MM_BSTR + bc * 4 + j * 32) * 4;
                asm volatile("cp.async.cg.shared.global [%0], [%1], 16;"
                             :: "r"(d), "l"(B + (size_t)(k0 + br) * HCd + col0 + bc * 4 + j * 32));
            }
            asm volatile("cp.async.commit_group;" ::: "memory");
            asm volatile("cp.async.wait_group 1;" ::: "memory");
        } else {
            asm volatile("cp.async.commit_group;" ::: "memory");
            asm volatile("cp.async.wait_group 0;" ::: "memory");
        }
        __syncthreads();

        const float* sA = smem + (kt & 1) * MM_STAGEF;
        const float* sB = sA + 128 * MM_ASTR;
#pragma unroll
        for (int ks = 0; ks < 4; ks++) {
            uint32_t af[2][4], bf[8][2];
#pragma unroll
            for (int mf = 0; mf < 2; mf++) {
                int m = warp_m * 32 + mf * 16 + lg;
                int k = ks * 8 + lk;
                af[mf][0] = __float_as_uint(sA[m * MM_ASTR + k]);
                af[mf][1] = __float_as_uint(sA[(m + 8) * MM_ASTR + k]);
                af[mf][2] = __float_as_uint(sA[m * MM_ASTR + k + 4]);
                af[mf][3] = __float_as_uint(sA[(m + 8) * MM_ASTR + k + 4]);
            }
#pragma unroll
            for (int nf = 0; nf < 8; nf++) {
                int n = warp_n * 64 + nf * 8 + lg;
                int k = ks * 8 + lk;
                bf[nf][0] = __float_as_uint(sB[k * MM_BSTR + n]);
                bf[nf][1] = __float_as_uint(sB[(k + 4) * MM_BSTR + n]);
            }
#pragma unroll
            for (int mf = 0; mf < 2; mf++)
#pragma unroll
                for (int nf = 0; nf < 8; nf++) mma8(acc[mf][nf], af[mf], bf[nf]);
        }
        __syncthreads();
    }

#pragma unroll
    for (int mf = 0; mf < 2; mf++) {
        int r0 = row0 + warp_m * 32 + mf * 16 + lg;
        int r1 = r0 + 8;
#pragma unroll
        for (int nf = 0; nf < 8; nf++) {
            int ccol = col0 + warp_n * 64 + nf * 8 + 2 * lk;
            if (r0 < M) *(float2*)(C + (size_t)r0 * HCd + ccol) =
                make_float2(acc[mf][nf][0], acc[mf][nf][1]);
            if (r1 < M) *(float2*)(C + (size_t)r1 * HCd + ccol) =
                make_float2(acc[mf][nf][2], acc[mf][nf][3]);
        }
    }
}

// ---------------- attention pieces --------------------------------------
__global__ void k_attn(const float* __restrict__ xl, const float* __restrict__ a_s,
                       const float* __restrict__ a_d) {
    int gw = (blockIdx.x * blockDim.x + threadIdx.x) >> 5;
    int lane = threadIdx.x & 31;
    if (gw >= Nn * Hh) return;
    int n = gw >> 3, h = gw & 7;
    float4 xv = *(const float4*)(xl + (size_t)n * HCd + h * Cc + lane * 4);
    float4 sv = *(const float4*)(a_s + h * Cc + lane * 4);
    float4 dv = *(const float4*)(a_d + h * Cc + lane * 4);
    float s1 = xv.x * sv.x + xv.y * sv.y + xv.z * sv.z + xv.w * sv.w;
    float s2 = xv.x * dv.x + xv.y * dv.y + xv.z * dv.z + xv.w * dv.w;
#pragma unroll
    for (int o = 16; o; o >>= 1) {
        s1 += __shfl_xor_sync(0xffffffffu, s1, o);
        s2 += __shfl_xor_sync(0xffffffffu, s2, o);
    }
    if (lane == 0) {
        g_asrc[n * 8 + h] = s1;
        g_adst[n * 8 + h] = s2;
    }
}

__global__ void k_v(const float* __restrict__ We, const float* __restrict__ ae) {
    int w = threadIdx.x >> 5, lane = threadIdx.x & 31;
    if (w >= 24) return;
    int f = w >> 3, h = w & 7;
    float s = 0.f;
    for (int i = lane; i < Cc; i += 32) s += We[f * HCd + h * Cc + i] * ae[h * Cc + i];
#pragma unroll
    for (int o = 16; o; o >>= 1) s += __shfl_xor_sync(0xffffffffu, s, o);
    if (lane == 0) g_v[f * 8 + h] = s;
}

// block per node; warp = head; lane owns 4 consecutive cols.
// Softmax shift c = self-edge alpha (node-local; shift-invariance of softmax).
__global__ __launch_bounds__(256) void k_agg(const float* __restrict__ xl,
                                             const float* __restrict__ ea,
                                             const float* __restrict__ bias,
                                             float* __restrict__ out, int mode) {
    int n = blockIdx.x;
    int lane = threadIdx.x & 31;
    int h = threadIdx.x >> 5;
    int col = h * Cc + lane * 4;

    float vh0 = g_v[h], vh1 = g_v[8 + h], vh2 = g_v[16 + h];
    float adh = g_adst[n * 8 + h];
    float ash = g_asrc[n * 8 + h];
    float l0 = g_loop[n * 3 + 0], l1 = g_loop[n * 3 + 1], l2 = g_loop[n * 3 + 2];
    float sae = l0 * vh0 + l1 * vh1 + l2 * vh2;
    float c = lrelu(ash + adh + sae);   // self-edge alpha as softmax shift

    // self contribution: exp(c - c) = 1
    float4 xv = *(const float4*)(xl + (size_t)n * HCd + col);
    float4 acc = xv;
    float den = 1.f;

    int s = g_off[n], tend = g_off[n + 1];
#pragma unroll 2
    for (int idx = s; idx < tend; idx++) {
        int e = g_eid[idx];
        int sn = g_csrc[idx];
        float q0 = ea[e * 3 + 0], q1 = ea[e * 3 + 1], q2 = ea[e * 3 + 2];
        float asn = g_asrc[sn * 8 + h];
        float aeh = q0 * vh0 + q1 * vh1 + q2 * vh2;
        float w = __expf(lrelu(asn + adh + aeh) - c);
        float4 xr = *(const float4*)(xl + (size_t)sn * HCd + col);
        acc.x += w * xr.x;
        acc.y += w * xr.y;
        acc.z += w * xr.z;
        acc.w += w * xr.w;
        den += w;
    }

    float inv = 1.f / (den + 1e-16f);
    float4 v = make_float4(acc.x * inv, acc.y * inv, acc.z * inv, acc.w * inv);
    if (mode == 0) {
        float4 b = *(const float4*)(bias + col);
        v.x += b.x; v.y += b.y; v.z += b.z; v.w += b.w;
        v.x = v.x > 0.f ? v.x : expm1f(v.x);
        v.y = v.y > 0.f ? v.y : expm1f(v.y);
        v.z = v.z > 0.f ? v.z : expm1f(v.z);
        v.w = v.w > 0.f ? v.w : expm1f(v.w);
        v.x = tf32r(v.x); v.y = tf32r(v.y); v.z = tf32r(v.z); v.w = tf32r(v.w);
    }
    *(float4*)(out + (size_t)n * HCd + col) = v;
}

__global__ void k_head(const float* __restrict__ tmp, const float* __restrict__ b4) {
    int idx = blockIdx.x * blockDim.x + threadIdx.x;
    if (idx >= Nn * Cc) return;
    int n = idx >> 7, c = idx & 127;
    float s = 0.f;
#pragma unroll
    for (int h = 0; h < 8; h++) s += tmp[(size_t)n * HCd + h * Cc + c];
    float v = s * 0.125f + b4[c];
    g_h4[idx] = v > 0.f ? v : expm1f(v);
}

__global__ void k_pool(const float* __restrict__ lw, const float* __restrict__ lb,
                       float* __restrict__ outp) {
    int g = blockIdx.x, c = threadIdx.x;
    int s = g_gstart[g], cnt = g_gcnt[g];
    float acc = 0.f;
    for (int i = 0; i < cnt; i++) acc += g_h4[(size_t)(s + i) * Cc + c];
    acc *= lw[c];
    __shared__ float red[128];
    red[c] = acc;
    __syncthreads();
    for (int o = 64; o; o >>= 1) {
        if (c < o) red[c] += red[c + o];
        __syncthreads();
    }
    if (c == 0) outp[g] = red[0] / fmaxf((float)cnt, 1.f) + lb[0];
}

// ---------------- launch -------------------------------------------------
static void* sym(const void* s) {
    void* p = nullptr;
    cudaGetSymbolAddress(&p, (const void*)s);
    return p;
}

extern "C" void kernel_launch(void* const* d_in, const int* in_sizes, int n_in,
                              void* d_out, int out_size) {
    (void)in_sizes; (void)n_in; (void)out_size;
    const float* x = (const float*)d_in[0];
    const int* ei = (const int*)d_in[1];
    const float* ea = (const float*)d_in[2];
    const int* batch = (const int*)d_in[3];
    const float *W[4], *We[4], *As_[4], *Ad_[4], *Ae_[4], *Bb[4];
    for (int l = 0; l < 4; l++) {
        W[l]   = (const float*)d_in[4 + 6 * l + 0];
        We[l]  = (const float*)d_in[4 + 6 * l + 1];
        As_[l] = (const float*)d_in[4 + 6 * l + 2];
        Ad_[l] = (const float*)d_in[4 + 6 * l + 3];
        Ae_[l] = (const float*)d_in[4 + 6 * l + 4];
        Bb[l]  = (const float*)d_in[4 + 6 * l + 5];
    }
    const float* lw = (const float*)d_in[28];
    const float* lb = (const float*)d_in[29];
    float* outp = (float*)d_out;

    float* xl = (float*)sym(&g_xl);
    float* hA = (float*)sym(&g_hA);
    float* hB = (float*)sym(&g_hB);
    float* Wr = (float*)sym(&g_Wr);

    cudaFuncSetAttribute(k_mma, cudaFuncAttributeMaxDynamicSharedMemorySize, MM_SMEM);

    cudaMemsetAsync(sym(&g_deg), 0, Nn * sizeof(int));
    cudaMemsetAsync(sym(&g_loopsum), 0, Nn * EFd * sizeof(float));
    cudaMemsetAsync(sym(&g_cur), 0, Nn * sizeof(int));
    cudaMemsetAsync(sym(&g_gcnt), 0, Gg * sizeof(int));
    k_initg<<<1, 32>>>();
    k_deg<<<(Ee + 255) / 256, 256>>>(ei, ea);
    k_scan<<<1, 256>>>();
    k_fill<<<(Ee + 255) / 256, 256>>>(ei);
    k_loop<<<(Nn + 255) / 256, 256>>>();
    k_bounds<<<(Nn + 255) / 256, 256>>>(batch);

    for (int l = 0; l < 4; l++) {
        const float* inp = (l == 0) ? x : ((l == 1) ? hA : ((l == 2) ? hB : hA));
        float* hout = (l == 0) ? hA : ((l == 1) ? hB : ((l == 2) ? hA : hB));

        if (l == 0) {
            k_gemm_small<<<(Nn * HCd + 255) / 256, 256>>>(x, W[0], xl);
        } else {
            k_round<<<(HCd * HCd + 255) / 256, 256>>>(W[l], Wr);
            k_mma<<<dim3(HCd / 128, (Nn + 127) / 128), 256, MM_SMEM>>>(inp, Wr, xl, Nn);
        }

        k_attn<<<(Nn * Hh * 32 + 255) / 256, 256>>>(xl, As_[l], Ad_[l]);
        k_v<<<1, 768>>>(We[l], Ae_[l]);
        k_agg<<<Nn, 256>>>(xl, ea, Bb[l], hout, (l < 3) ? 0 : 1);
        if (l == 3) k_head<<<(Nn * Cc + 255) / 256, 256>>>(hB, Bb[3]);
    }
    k_pool<<<Gg, 128>>>(lw, lb, outp);
}